// round 5
// baseline (speedup 1.0000x reference)
#include <cuda_runtime.h>

// Scalar damped-Newton minimization of a degree-6 polynomial.
// Inputs: d_in[0] = poly (7 x float32, lowest-degree first), d_in[1] = x_init (1 x f32)
// Output: 1 x float32 = x_min.
//
// Same fixed point as the JAX lax.while_loop:
//   while (g2 > 1e-12 && it < 100) { g=p'(x); h=p''(x);
//       step = h>0 ? g/h : 0.1*g; x -= step; g2 = p'(x)^2; it++ }
//
// Latency-bound single-thread kernel at the launch-overhead floor. This
// version overlaps the convergence test with the next iteration (test lags
// one step: at most one extra Newton step of size <= ~1e-6, far inside the
// 1e-3 tolerance) and computes rcp(h) speculatively so the MUFU starts the
// moment h is ready instead of after the h>0 predicate resolves.

#define MAX_ITER 100
#define GRAD_SQ_TOL 1e-12f

__global__ void polymin_kernel(const float4* __restrict__ poly4,
                               const float* __restrict__ x_init,
                               float* __restrict__ out) {
    const float2* poly2 = (const float2*)poly4;
    const float*  polyf = (const float*)poly4;

    // 3 back-to-back LDGs (float4 + float2 + float) + x_init: MLP=4.
    float4 pA = poly4[0];        // c0..c3
    float2 pB = poly2[2];        // c4, c5
    float  c6 = polyf[6];
    float  x  = x_init[0];

    // p'(x) coefficients (degree 5) — FMULs hidden in the load shadow.
    float d1_0 = pA.y;
    float d1_1 = pA.z * 2.0f;
    float d1_2 = pA.w * 3.0f;
    float d1_3 = pB.x * 4.0f;
    float d1_4 = pB.y * 5.0f;
    float d1_5 = c6   * 6.0f;

    // p''(x) coefficients (degree 4)
    float d2_0 = d1_1;
    float d2_1 = d1_2 * 2.0f;
    float d2_2 = d1_3 * 3.0f;
    float d2_3 = d1_4 * 4.0f;
    float d2_4 = d1_5 * 5.0f;

    // g = p'(x) via Estrin (3 dependent levels).
    float x2 = x * x;
    float g  = fmaf(fmaf(fmaf(d1_5, x, d1_4), x2, fmaf(d1_3, x, d1_2)), x2,
                    fmaf(d1_1, x, d1_0));

    #pragma unroll 1
    for (int it = 0; it < MAX_ITER; ++it) {
        // Convergence test on the CURRENT g (lagged relative to the update
        // below) — fully overlapped with the x-critical path.
        if (!(g * g > GRAD_SQ_TOL)) break;

        // h = p''(x), Estrin from x (3 dependent levels).
        float h = fmaf(fmaf(fmaf(d2_4, x, d2_3), x, d2_2), x2,
                       fmaf(d2_1, x, d2_0));

        // Speculative reciprocal: MUFU.RCP issues at h-ready; the h>0
        // predicate resolves in parallel and selects the multiplier.
        float r    = __frcp_rn(h);
        float mult = (h > 0.0f) ? r : 0.1f;
        x = fmaf(-g, mult, x);

        // Carried gradient: g = p'(x_new), feeds next step AND next test.
        x2 = x * x;
        g  = fmaf(fmaf(fmaf(d1_5, x, d1_4), x2, fmaf(d1_3, x, d1_2)), x2,
                  fmaf(d1_1, x, d1_0));
    }

    out[0] = x;
}

extern "C" void kernel_launch(void* const* d_in, const int* in_sizes, int n_in,
                              void* d_out, int out_size) {
    polymin_kernel<<<1, 1>>>((const float4*)d_in[0], (const float*)d_in[1],
                             (float*)d_out);
}

// round 7
// speedup vs baseline: 1.4150x; 1.4150x over previous
#include <cuda_runtime.h>

// Scalar damped-Newton minimization of a degree-6 polynomial.
// Inputs: d_in[0] = poly (7 x float32, lowest-degree first), d_in[1] = x_init (1 x f32)
// Output: 1 x float32 = x_min.
//
// Same fixed point as the JAX lax.while_loop:
//   while (g2 > 1e-12 && it < 100) { g=p'(x); h=p''(x);
//       step = h>0 ? g/h : 0.1*g; x -= step; g2 = p'(x)^2; it++ }
//
// Latency-bound single-thread kernel at the single-CTA launch-overhead floor.
// Critical-path choices:
//  - 3 vectorized input LDGs (float4+float2+float) + x_init, MLP=4.
//  - Estrin evaluation (3 dependent FMA levels for p', p'').
//  - Carried gradient: p'(x) evaluated once per iteration.
//  - Lagged convergence test: exit chain overlaps the x-update chain
//    (at most one extra ~1e-6 Newton step; same fixed point).
//  - Speculative single-MUFU rcp.approx, selected against 0.1 by the h>0
//    predicate in parallel.

#define MAX_ITER 100
#define GRAD_SQ_TOL 1e-12f

__device__ __forceinline__ float rcp_approx(float a) {
    float r;
    asm("rcp.approx.ftz.f32 %0, %1;" : "=f"(r) : "f"(a));
    return r;
}

__global__ void polymin_kernel(const float4* __restrict__ poly4,
                               const float* __restrict__ x_init,
                               float* __restrict__ out) {
    const float2* poly2 = (const float2*)poly4;
    const float*  polyf = (const float*)poly4;

    float4 pA = poly4[0];        // c0..c3
    float2 pB = poly2[2];        // c4, c5
    float  c6 = polyf[6];
    float  x  = x_init[0];

    // p'(x) coefficients (degree 5) — FMULs hidden in the load shadow.
    float d1_0 = pA.y;
    float d1_1 = pA.z * 2.0f;
    float d1_2 = pA.w * 3.0f;
    float d1_3 = pB.x * 4.0f;
    float d1_4 = pB.y * 5.0f;
    float d1_5 = c6   * 6.0f;

    // p''(x) coefficients (degree 4)
    float d2_0 = d1_1;
    float d2_1 = d1_2 * 2.0f;
    float d2_2 = d1_3 * 3.0f;
    float d2_3 = d1_4 * 4.0f;
    float d2_4 = d1_5 * 5.0f;

    // g = p'(x) via Estrin (3 dependent levels).
    float x2 = x * x;
    float g  = fmaf(fmaf(fmaf(d1_5, x, d1_4), x2, fmaf(d1_3, x, d1_2)), x2,
                    fmaf(d1_1, x, d1_0));

    #pragma unroll 1
    for (int it = 0; it < MAX_ITER; ++it) {
        // Lagged convergence test — overlaps the x-critical path.
        if (!(g * g > GRAD_SQ_TOL)) break;

        // h = p''(x), Estrin from x.
        float h = fmaf(fmaf(fmaf(d2_4, x, d2_3), x, d2_2), x2,
                       fmaf(d2_1, x, d2_0));

        // Speculative MUFU reciprocal; predicate select runs in parallel.
        float r    = rcp_approx(h);
        float mult = (h > 0.0f) ? r : 0.1f;
        x = fmaf(-g, mult, x);

        // Carried gradient: g = p'(x_new), feeds next step AND next test.
        x2 = x * x;
        g  = fmaf(fmaf(fmaf(d1_5, x, d1_4), x2, fmaf(d1_3, x, d1_2)), x2,
                  fmaf(d1_1, x, d1_0));
    }

    out[0] = x;
}

extern "C" void kernel_launch(void* const* d_in, const int* in_sizes, int n_in,
                              void* d_out, int out_size) {
    polymin_kernel<<<1, 1>>>((const float4*)d_in[0], (const float*)d_in[1],
                             (float*)d_out);
}

// round 8
// speedup vs baseline: 1.4444x; 1.0208x over previous
#include <cuda_runtime.h>

// Scalar damped-Newton minimization of a degree-6 polynomial.
// Inputs: d_in[0] = poly (7 x float32, lowest-degree first), d_in[1] = x_init (1 x f32)
// Output: 1 x float32 = x_min.
//
// Same fixed point as the JAX lax.while_loop:
//   while (g2 > 1e-12 && it < 100) { g=p'(x); h=p''(x);
//       step = h>0 ? g/h : 0.1*g; x -= step; g2 = p'(x)^2; it++ }
//
// Latency-bound single-thread kernel at the single-CTA launch-overhead floor.
//  - 3 vectorized input LDGs (float4+float2+float) + x_init, MLP=4.
//  - Estrin evaluation (3 dependent FMA levels for p', p'').
//  - Carried gradient: p'(x) evaluated once per Newton step.
//  - Speculative single-MUFU rcp.approx, FSEL'd against 0.1 by h>0.
//  - Loop unrolled 2x with one convergence test per pair: post-convergence
//    steps are no-ops at the fixed point (|step| ~ 1e-7), so at most 2 extra
//    harmless steps — same fixed point, halved branch overhead.

#define GRAD_SQ_TOL 1e-12f

__device__ __forceinline__ float rcp_approx(float a) {
    float r;
    asm("rcp.approx.ftz.f32 %0, %1;" : "=f"(r) : "f"(a));
    return r;
}

__global__ void polymin_kernel(const float4* __restrict__ poly4,
                               const float* __restrict__ x_init,
                               float* __restrict__ out) {
    const float2* poly2 = (const float2*)poly4;
    const float*  polyf = (const float*)poly4;

    float4 pA = poly4[0];        // c0..c3
    float2 pB = poly2[2];        // c4, c5
    float  c6 = polyf[6];
    float  x  = x_init[0];

    // p'(x) coefficients (degree 5) — FMULs hidden in the load shadow.
    float d1_0 = pA.y;
    float d1_1 = pA.z * 2.0f;
    float d1_2 = pA.w * 3.0f;
    float d1_3 = pB.x * 4.0f;
    float d1_4 = pB.y * 5.0f;
    float d1_5 = c6   * 6.0f;

    // p''(x) coefficients (degree 4)
    float d2_0 = d1_1;
    float d2_1 = d1_2 * 2.0f;
    float d2_2 = d1_3 * 3.0f;
    float d2_3 = d1_4 * 4.0f;
    float d2_4 = d1_5 * 5.0f;

    // g = p'(x) via Estrin (3 dependent levels).
    float x2 = x * x;
    float g  = fmaf(fmaf(fmaf(d1_5, x, d1_4), x2, fmaf(d1_3, x, d1_2)), x2,
                    fmaf(d1_1, x, d1_0));

    #pragma unroll 1
    for (int it = 0; it < 50; ++it) {
        // One convergence test per two Newton steps (lagged; overlaps both
        // step chains).
        if (!(g * g > GRAD_SQ_TOL)) break;

        // ---- step A ----
        float h = fmaf(fmaf(fmaf(d2_4, x, d2_3), x, d2_2), x2,
                       fmaf(d2_1, x, d2_0));
        float r    = rcp_approx(h);
        float mult = (h > 0.0f) ? r : 0.1f;
        x  = fmaf(-g, mult, x);
        x2 = x * x;
        g  = fmaf(fmaf(fmaf(d1_5, x, d1_4), x2, fmaf(d1_3, x, d1_2)), x2,
                  fmaf(d1_1, x, d1_0));

        // ---- step B (untested; harmless past convergence) ----
        h = fmaf(fmaf(fmaf(d2_4, x, d2_3), x, d2_2), x2,
                 fmaf(d2_1, x, d2_0));
        r    = rcp_approx(h);
        mult = (h > 0.0f) ? r : 0.1f;
        x  = fmaf(-g, mult, x);
        x2 = x * x;
        g  = fmaf(fmaf(fmaf(d1_5, x, d1_4), x2, fmaf(d1_3, x, d1_2)), x2,
                  fmaf(d1_1, x, d1_0));
    }

    out[0] = x;
}

extern "C" void kernel_launch(void* const* d_in, const int* in_sizes, int n_in,
                              void* d_out, int out_size) {
    polymin_kernel<<<1, 1>>>((const float4*)d_in[0], (const float*)d_in[1],
                             (float*)d_out);
}